// round 3
// baseline (speedup 1.0000x reference)
#include <cuda_runtime.h>

// Linear RNN h_t = x_t@W + h_{t-1}@R via log-doubling scan.
// Time-major internal layout [T, B, U] (row r = t*32 + b) so temporal shifts
// are contiguous row offsets. 5 doubling levels (shift d = 1,2,4,8,16 steps
// with R^d), then 31 sequential chunk-steps with R^32; scan epilogue writes
// the final [B,T,U] output directly.

#define NROWS 32768   // B*T
#define UDIM  1024

__device__ float g_bufA[33554432];   // 128 MB scratch (time-major [T*B, U])
__device__ float g_bufB[33554432];   // 128 MB scratch
__device__ float g_pow[5][1048576];  // R^2, R^4, R^8, R^16, R^32

constexpr int TMX = 128;
constexpr int BKX = 8;

// MODE 0: C = A @ Bm                       (plain; used for R-power chain)
// MODE 1: C[r] = x[xmap(r)] @ Bm           (xW with [B,T,D] -> time-major map)
// MODE 2: C[r] = S[r] + (r>=shift ? A[r-shift] @ Bm : 0)   (doubling level)
// MODE 3: C[r] += A[r] @ Bm ; optional transposed dual-write to OUT (scan step / h0 fold)
template<int TN, int MODE>
__global__ void __launch_bounds__(256) gemm_k(
    const float* __restrict__ A, const float* __restrict__ Bm,
    const float* __restrict__ S, float* C, float* OUT,
    int M, int N, int K, int shift, int rowOff)
{
    __shared__ float As[BKX][TMX];
    __shared__ float Bs[BKX][TN];
    const int tid = threadIdx.x;
    const int rowTile = blockIdx.y * TMX;
    const int colBase = blockIdx.x * TN;
    constexpr int CW = TN / 16;
    const int ty = tid >> 4, tx = tid & 15;

    // ---- A tile load mapping (row fixed across K-chunks) ----
    int r = rowTile + (tid >> 1);
    int rc = (r < M) ? r : (M - 1);
    int arow;
    if (MODE == 1) {
        arow = ((rc & 31) << 10) + (rc >> 5);      // x[b,t,:] row = b*1024 + t
    } else if (MODE == 2) {
        arow = r - shift;
        if (arow < 0) arow = 0;                    // discarded by epilogue predicate
    } else {
        arow = rc;
    }
    const float* aPtr = A + (size_t)arow * K + ((tid & 1) << 2);

    // ---- B tile load mapping ----
    bool bAct; int bRow, bCol;
    if (TN == 128) { bAct = true;        bRow = tid >> 5; bCol = (tid & 31) << 2; }
    else           { bAct = (tid < 128); bRow = tid >> 4; bCol = (tid & 15) << 2; }
    const float* bPtr = Bm + (size_t)bRow * N + colBase + bCol;

    float4 aReg = *(const float4*)aPtr;
    float4 bReg = bAct ? *(const float4*)bPtr : make_float4(0.f, 0.f, 0.f, 0.f);

    float acc[8][CW];
    #pragma unroll
    for (int i = 0; i < 8; i++)
        #pragma unroll
        for (int j = 0; j < CW; j++) acc[i][j] = 0.f;

    for (int kc = 0; kc < K; kc += BKX) {
        // stage prefetched regs into smem
        {
            int ar = tid >> 1, ak = (tid & 1) << 2;
            As[ak + 0][ar] = aReg.x; As[ak + 1][ar] = aReg.y;
            As[ak + 2][ar] = aReg.z; As[ak + 3][ar] = aReg.w;
            if (bAct) *(float4*)&Bs[bRow][bCol] = bReg;
        }
        __syncthreads();
        if (kc + BKX < K) {   // prefetch next chunk while computing this one
            aReg = *(const float4*)(aPtr + (kc + BKX));
            if (bAct) bReg = *(const float4*)(bPtr + (size_t)(kc + BKX) * N);
        }
        #pragma unroll
        for (int k = 0; k < BKX; k++) {
            float a[8];
            float4 a0 = *(float4*)&As[k][ty * 8];
            float4 a1 = *(float4*)&As[k][ty * 8 + 4];
            a[0]=a0.x; a[1]=a0.y; a[2]=a0.z; a[3]=a0.w;
            a[4]=a1.x; a[5]=a1.y; a[6]=a1.z; a[7]=a1.w;
            float b[CW];
            if (CW == 8) {
                float4 b0 = *(float4*)&Bs[k][tx * 8];
                float4 b1 = *(float4*)&Bs[k][tx * 8 + 4];
                b[0]=b0.x; b[1]=b0.y; b[2]=b0.z; b[3]=b0.w;
                b[4]=b1.x; b[5]=b1.y; b[6]=b1.z; b[7]=b1.w;
            } else {
                float4 b0 = *(float4*)&Bs[k][tx * 4];
                b[0]=b0.x; b[1]=b0.y; b[2]=b0.z; b[3]=b0.w;
            }
            #pragma unroll
            for (int i = 0; i < 8; i++)
                #pragma unroll
                for (int j = 0; j < CW; j++)
                    acc[i][j] += a[i] * b[j];
        }
        __syncthreads();
    }

    // ---- epilogue ----
    #pragma unroll
    for (int i = 0; i < 8; i++) {
        int rr = rowTile + ty * 8 + i;
        if (rr >= M) continue;
        float* cp = C + (size_t)rr * N + colBase + tx * CW;
        if (MODE == 2) {
            const float* sp = S + (size_t)rr * N + colBase + tx * CW;
            bool live = (rr >= shift);
            #pragma unroll
            for (int j = 0; j < CW; j++)
                cp[j] = sp[j] + (live ? acc[i][j] : 0.f);
        } else if (MODE == 3) {
            float res[CW];
            #pragma unroll
            for (int j = 0; j < CW; j++) { res[j] = cp[j] + acc[i][j]; cp[j] = res[j]; }
            if (OUT != nullptr) {
                int g = rowOff + rr;                 // global time-major row
                float* op = OUT + (size_t)((g & 31) * 1024 + (g >> 5)) * N
                                + colBase + tx * CW; // [B,T,U] position
                #pragma unroll
                for (int j = 0; j < CW; j++) op[j] = res[j];
            }
        } else {
            #pragma unroll
            for (int j = 0; j < CW; j++) cp[j] = acc[i][j];
        }
    }
}

// First chunk (t < 32) is final after level 5: transpose-copy it to d_out.
__global__ void copy_chunk0(const float* __restrict__ src, float* __restrict__ OUT)
{
    int i = blockIdx.x * blockDim.x + threadIdx.x;   // over 1024 rows * 256 float4
    int g = i >> 8;
    int c = (i & 255) << 2;
    float4 v = *(const float4*)(src + (size_t)g * 1024 + c);
    *(float4*)(OUT + (size_t)((g & 31) * 1024 + (g >> 5)) * 1024 + c) = v;
}

extern "C" void kernel_launch(void* const* d_in, const int* in_sizes, int n_in,
                              void* d_out, int out_size)
{
    const float* x  = (const float*)d_in[0];   // [32,1024,512]
    const float* h0 = (const float*)d_in[1];   // [32,1024]
    const float* W  = (const float*)d_in[2];   // [512,1024]
    const float* R  = (const float*)d_in[3];   // [1024,1024]
    float* out = (float*)d_out;                // [32,1024,1024]

    float *bufA, *bufB, *gp;
    cudaGetSymbolAddress((void**)&bufA, g_bufA);
    cudaGetSymbolAddress((void**)&bufB, g_bufB);
    cudaGetSymbolAddress((void**)&gp,   g_pow);
    float* P[5];
    for (int i = 0; i < 5; i++) P[i] = gp + (size_t)i * 1048576;

    dim3 blk(256);
    dim3 g64(16, 8);     // TN=64 tiles for 1024-row GEMMs
    dim3 g128(8, 256);   // TN=128 tiles for 32768-row GEMMs

    // R-power chain: R^2, R^4, R^8, R^16, R^32
    gemm_k<64, 0><<<g64, blk>>>(R,    R,    nullptr, P[0], nullptr, 1024, 1024, 1024, 0, 0);
    gemm_k<64, 0><<<g64, blk>>>(P[0], P[0], nullptr, P[1], nullptr, 1024, 1024, 1024, 0, 0);
    gemm_k<64, 0><<<g64, blk>>>(P[1], P[1], nullptr, P[2], nullptr, 1024, 1024, 1024, 0, 0);
    gemm_k<64, 0><<<g64, blk>>>(P[2], P[2], nullptr, P[3], nullptr, 1024, 1024, 1024, 0, 0);
    gemm_k<64, 0><<<g64, blk>>>(P[3], P[3], nullptr, P[4], nullptr, 1024, 1024, 1024, 0, 0);

    // b0 = xW into bufA (time-major)
    gemm_k<128, 1><<<g128, blk>>>(x, W, nullptr, bufA, nullptr, NROWS, UDIM, 512, 0, 0);

    // fold initial state: rows t=0 get += h0 @ R
    gemm_k<64, 3><<<dim3(16, 1), blk>>>(h0, R, nullptr, bufA, nullptr, 32, UDIM, 1024, 0, 0);

    // 5 doubling levels (shift in rows = 32 * 2^(l-1)), ping-pong bufA<->bufB
    gemm_k<128, 2><<<g128, blk>>>(bufA, R,    bufA, bufB, nullptr, NROWS, UDIM, 1024,  32, 0);
    gemm_k<128, 2><<<g128, blk>>>(bufB, P[0], bufB, bufA, nullptr, NROWS, UDIM, 1024,  64, 0);
    gemm_k<128, 2><<<g128, blk>>>(bufA, P[1], bufA, bufB, nullptr, NROWS, UDIM, 1024, 128, 0);
    gemm_k<128, 2><<<g128, blk>>>(bufB, P[2], bufB, bufA, nullptr, NROWS, UDIM, 1024, 256, 0);
    gemm_k<128, 2><<<g128, blk>>>(bufA, P[3], bufA, bufB, nullptr, NROWS, UDIM, 1024, 512, 0);

    // sequential scan over 32 chunks of 32 timesteps: h_chunk += h_prev @ R^32,
    // dual-writing final values transposed into d_out
    for (int s = 1; s < 32; s++) {
        gemm_k<64, 3><<<g64, blk>>>(bufB + (size_t)(s - 1) * 1024 * 1024, P[4], nullptr,
                                    bufB + (size_t)s * 1024 * 1024, out,
                                    1024, UDIM, 1024, 0, s * 1024);
    }

    // chunk 0 (t < 32) is already final in bufB; transpose-copy to d_out
    copy_chunk0<<<1024, 256>>>(bufB, out);

    (void)in_sizes; (void)n_in; (void)out_size;
}

// round 5
// speedup vs baseline: 3.2077x; 3.2077x over previous
#include <cuda_runtime.h>
#include <cuda_bf16.h>
#include <cstdint>

// Linear RNN h_t = x_t@W + h_{t-1}@R via log-doubling scan (validated in R1),
// GEMM core = warp-level mma.sync bf16 (HMMA) with hi/lo split (3 passes,
// fp32 accum). No "a"-suffix PTX features (harness targets sm_103 baseline).

#define UD 1024
#define BT 32768

// ---------------- scratch ----------------
__device__ __nv_bfloat16 g_s0h[33554432];
__device__ __nv_bfloat16 g_s0l[33554432];
__device__ __nv_bfloat16 g_s1h[33554432];
__device__ __nv_bfloat16 g_s1l[33554432];
__device__ __nv_bfloat16 g_xh[16777216];
__device__ __nv_bfloat16 g_xl[16777216];
__device__ __nv_bfloat16 g_h0h[32768];
__device__ __nv_bfloat16 g_h0l[32768];
__device__ __nv_bfloat16 g_wth[524288];
__device__ __nv_bfloat16 g_wtl[524288];
__device__ __nv_bfloat16 g_ph [5][1048576];
__device__ __nv_bfloat16 g_pl [5][1048576];
__device__ __nv_bfloat16 g_pth[5][1048576];
__device__ __nv_bfloat16 g_ptl[5][1048576];
__device__ __nv_bfloat16 g_p32th[1048576];
__device__ __nv_bfloat16 g_p32tl[1048576];

// ---------------- helpers ----------------
__device__ __forceinline__ uint32_t smem_u32(const void* p) {
    uint32_t a;
    asm("{ .reg .u64 t; cvta.to.shared.u64 t, %1; cvt.u32.u64 %0, t; }"
        : "=r"(a) : "l"(p));
    return a;
}
__device__ __forceinline__ void cpa16(uint32_t d, const void* s) {
    asm volatile("cp.async.cg.shared.global [%0], [%1], 16;" :: "r"(d), "l"(s) : "memory");
}
#define CPA_COMMIT() asm volatile("cp.async.commit_group;" ::: "memory")

__device__ __forceinline__ uint32_t pk(__nv_bfloat16 a, __nv_bfloat16 b) {
    return (uint32_t)__bfloat16_as_ushort(a) | ((uint32_t)__bfloat16_as_ushort(b) << 16);
}
__device__ __forceinline__ void split4(float4 v, uint2& h, uint2& l) {
    __nv_bfloat16 h0 = __float2bfloat16(v.x), h1 = __float2bfloat16(v.y);
    __nv_bfloat16 h2 = __float2bfloat16(v.z), h3 = __float2bfloat16(v.w);
    __nv_bfloat16 l0 = __float2bfloat16(v.x - __bfloat162float(h0));
    __nv_bfloat16 l1 = __float2bfloat16(v.y - __bfloat162float(h1));
    __nv_bfloat16 l2 = __float2bfloat16(v.z - __bfloat162float(h2));
    __nv_bfloat16 l3 = __float2bfloat16(v.w - __bfloat162float(h3));
    h.x = pk(h0, h1); h.y = pk(h2, h3);
    l.x = pk(l0, l1); l.y = pk(l2, l3);
}

// ======================= HMMA GEMM =======================
// C[m,n] = sum_k A[m,k]*Bt[n,k]  (Bt K-major [N,K] = B transposed)
// hi/lo 3-pass folded into one K loop: seg phase 0: Ah*Bh, 1: Al*Bh, 2: Ah*Bl
// MODE 0: C = A@B
// MODE 1: C[r] = S[r] + (r>=shift ? A[r-shift]@B : 0)
// MODE 2: C[r] = S[r] + A[r]@B ; optional fp32 transposed dual-write to OUT
template<int TN, int MODE>
__global__ void __launch_bounds__(256, 2) tgemm(
    const __nv_bfloat16* __restrict__ Ah, const __nv_bfloat16* __restrict__ Al,
    const __nv_bfloat16* __restrict__ Bh, const __nv_bfloat16* __restrict__ Bl,
    const __nv_bfloat16* __restrict__ Sh, const __nv_bfloat16* __restrict__ Sl,
    __nv_bfloat16* __restrict__ Ch, __nv_bfloat16* __restrict__ Cl,
    float* __restrict__ OUT,
    int M, int Kd, int shift, int rowOff)
{
    constexpr int AB  = 128 * 80;          // A tile bytes (128 rows x 32 bf16, 80B padded)
    constexpr int BB  = TN * 80;
    constexpr int STG = AB + BB;
    __shared__ __align__(128) char smem_[2 * STG];

    const int tid  = threadIdx.x;
    const int wid  = tid >> 5, lane = tid & 31;
    const int rowTile = blockIdx.y * 128;
    const int colBase = blockIdx.x * TN;
    const int wr = wid >> 1, wc = wid & 1;
    constexpr int WCOL = TN / 2;           // warp col extent
    constexpr int NN   = WCOL / 8;         // n8 tiles per warp
    const int wcBase = wc * WCOL;

    const uint32_t sb = smem_u32(smem_);
    const int nk   = Kd >> 5;
    const int nSeg = 3 * nk;

    auto load_stage = [&](int buf, int seg) {
        int phase = (seg >= nk) + (seg >= 2 * nk);
        int ks = seg - phase * nk;
        const __nv_bfloat16* Ap = (phase == 1) ? Al : Ah;
        const __nv_bfloat16* Bp = (phase == 2) ? Bl : Bh;
        const int koff = ks * 32;
        const uint32_t abase = sb + buf * STG;
        const uint32_t bbase = abase + AB;
        #pragma unroll
        for (int i = 0; i < 2; i++) {                       // A: 512 chunks
            int t = tid + i * 256;
            int row = t >> 2, ch = t & 3;
            int r = rowTile + row;
            int ar = (MODE == 1) ? r - shift : r;
            ar = ar < 0 ? 0 : (ar > M - 1 ? M - 1 : ar);
            cpa16(abase + row * 80 + ch * 16,
                  Ap + (size_t)ar * Kd + koff + ch * 8);
        }
        #pragma unroll
        for (int i = 0; i < TN / 64; i++) {                 // B: TN*4 chunks
            int t = tid + i * 256;
            int row = t >> 2, ch = t & 3;
            cpa16(bbase + row * 80 + ch * 16,
                  Bp + (size_t)(colBase + row) * Kd + koff + ch * 8);
        }
    };

    // ldmatrix per-lane offsets (bytes within tile)
    const uint32_t aoff0 = (uint32_t)((wr * 32 + (lane & 15)) * 80 + (lane >> 4) * 16);
    const int nB = wcBase + ((lane >> 4) << 3) + (lane & 7);
    const uint32_t boff0 = (uint32_t)(nB * 80 + ((lane >> 3) & 1) * 16);

    float acc[2][NN][4] = {};

    load_stage(0, 0); CPA_COMMIT();
    load_stage(1, 1); CPA_COMMIT();

    for (int s = 0; s < nSeg; s++) {
        asm volatile("cp.async.wait_group 1;" ::: "memory");
        __syncthreads();
        const uint32_t abase = sb + (s & 1) * STG;
        const uint32_t bbase = abase + AB;
        #pragma unroll
        for (int k16 = 0; k16 < 2; k16++) {
            uint32_t a[2][4], b[NN][2];
            #pragma unroll
            for (int mi = 0; mi < 2; mi++) {
                uint32_t ad = abase + aoff0 + mi * (16 * 80) + k16 * 32;
                asm volatile("ldmatrix.sync.aligned.m8n8.x4.shared.b16 {%0,%1,%2,%3}, [%4];"
                    : "=r"(a[mi][0]), "=r"(a[mi][1]), "=r"(a[mi][2]), "=r"(a[mi][3])
                    : "r"(ad));
            }
            #pragma unroll
            for (int bj = 0; bj < NN / 2; bj++) {
                uint32_t bd = bbase + boff0 + bj * (16 * 80) + k16 * 32;
                asm volatile("ldmatrix.sync.aligned.m8n8.x4.shared.b16 {%0,%1,%2,%3}, [%4];"
                    : "=r"(b[2 * bj][0]), "=r"(b[2 * bj][1]),
                      "=r"(b[2 * bj + 1][0]), "=r"(b[2 * bj + 1][1])
                    : "r"(bd));
            }
            #pragma unroll
            for (int mi = 0; mi < 2; mi++)
                #pragma unroll
                for (int nj = 0; nj < NN; nj++)
                    asm volatile(
                        "mma.sync.aligned.m16n8k16.row.col.f32.bf16.bf16.f32 "
                        "{%0,%1,%2,%3}, {%4,%5,%6,%7}, {%8,%9}, {%0,%1,%2,%3};"
                        : "+f"(acc[mi][nj][0]), "+f"(acc[mi][nj][1]),
                          "+f"(acc[mi][nj][2]), "+f"(acc[mi][nj][3])
                        : "r"(a[mi][0]), "r"(a[mi][1]), "r"(a[mi][2]), "r"(a[mi][3]),
                          "r"(b[nj][0]), "r"(b[nj][1]));
        }
        __syncthreads();
        if (s + 2 < nSeg) load_stage(s & 1, s + 2);
        CPA_COMMIT();
    }

    // ---- epilogue ----
    #pragma unroll
    for (int mi = 0; mi < 2; mi++) {
        #pragma unroll
        for (int half = 0; half < 2; half++) {
            int rr = rowTile + wr * 32 + mi * 16 + half * 8 + (lane >> 2);
            if (rr >= M) continue;
            const bool live = (MODE != 1) || (rr >= shift);
            const size_t rb = (size_t)rr * UD;
            int g = rowOff + rr;
            float* op = (MODE == 2 && OUT != nullptr)
                      ? OUT + (size_t)((g & 31) * 1024 + (g >> 5)) * UD : nullptr;
            #pragma unroll
            for (int nj = 0; nj < NN; nj++) {
                int col = colBase + wcBase + nj * 8 + (lane & 3) * 2;
                float v0 = acc[mi][nj][half * 2];
                float v1 = acc[mi][nj][half * 2 + 1];
                if (MODE >= 1) {
                    __nv_bfloat162 sh2 = *(const __nv_bfloat162*)(Sh + rb + col);
                    __nv_bfloat162 sl2 = *(const __nv_bfloat162*)(Sl + rb + col);
                    float2 fh = __bfloat1622float2(sh2);
                    float2 fl = __bfloat1622float2(sl2);
                    v0 = fh.x + fl.x + (live ? v0 : 0.f);
                    v1 = fh.y + fl.y + (live ? v1 : 0.f);
                }
                __nv_bfloat16 h0_ = __float2bfloat16(v0), h1_ = __float2bfloat16(v1);
                __nv_bfloat16 l0_ = __float2bfloat16(v0 - __bfloat162float(h0_));
                __nv_bfloat16 l1_ = __float2bfloat16(v1 - __bfloat162float(h1_));
                *(uint32_t*)(Ch + rb + col) = pk(h0_, h1_);
                *(uint32_t*)(Cl + rb + col) = pk(l0_, l1_);
                if (op) { op[col] = v0; op[col + 1] = v1; }
            }
        }
    }
}

// ======================= pre/post kernels =======================
__global__ void split_x(const float* __restrict__ x,
                        __nv_bfloat16* __restrict__ oh, __nv_bfloat16* __restrict__ ol)
{
    int id = blockIdx.x * 256 + threadIdx.x;
    int r = id >> 7;                                  // time-major row t*32+b
    int c = (id & 127) << 2;
    int b = r & 31, t = r >> 5;
    float4 vv = *(const float4*)(x + (size_t)(b * 1024 + t) * 512 + c);
    uint2 h, l; split4(vv, h, l);
    *(uint2*)(oh + (size_t)r * 512 + c) = h;
    *(uint2*)(ol + (size_t)r * 512 + c) = l;
}

__global__ void split_plain(const float* __restrict__ in,
                            __nv_bfloat16* __restrict__ oh, __nv_bfloat16* __restrict__ ol)
{
    int id = blockIdx.x * 256 + threadIdx.x;
    float4 vv = *(const float4*)(in + (size_t)id * 4);
    uint2 h, l; split4(vv, h, l);
    *(uint2*)(oh + (size_t)id * 4) = h;
    *(uint2*)(ol + (size_t)id * 4) = l;
}

__global__ void tsplit(const float* __restrict__ in,
                       __nv_bfloat16* __restrict__ oh, __nv_bfloat16* __restrict__ ol,
                       int K, int N)
{
    __shared__ float tile[32][33];
    int nb = blockIdx.x * 32, kb = blockIdx.y * 32;
    int tx = threadIdx.x, ty = threadIdx.y;
    #pragma unroll
    for (int j = 0; j < 32; j += 8)
        tile[ty + j][tx] = in[(size_t)(kb + ty + j) * N + nb + tx];
    __syncthreads();
    #pragma unroll
    for (int j = 0; j < 32; j += 8) {
        float vv = tile[tx][ty + j];
        size_t o = (size_t)(nb + ty + j) * K + kb + tx;
        __nv_bfloat16 h = __float2bfloat16(vv);
        oh[o] = h;
        ol[o] = __float2bfloat16(vv - __bfloat162float(h));
    }
}

__global__ void copy0(const __nv_bfloat16* __restrict__ Sh,
                      const __nv_bfloat16* __restrict__ Sl, float* __restrict__ OUT)
{
    int id = blockIdx.x * 256 + threadIdx.x;
    int g = id >> 8;
    int c = (id & 255) << 2;
    size_t off = (size_t)g * UD + c;
    __nv_bfloat162 h01 = *(const __nv_bfloat162*)(Sh + off);
    __nv_bfloat162 h23 = *(const __nv_bfloat162*)(Sh + off + 2);
    __nv_bfloat162 l01 = *(const __nv_bfloat162*)(Sl + off);
    __nv_bfloat162 l23 = *(const __nv_bfloat162*)(Sl + off + 2);
    float2 a = __bfloat1622float2(h01), b = __bfloat1622float2(h23);
    float2 p = __bfloat1622float2(l01), q = __bfloat1622float2(l23);
    float* op = OUT + (size_t)((g & 31) * 1024 + (g >> 5)) * UD + c;
    *(float4*)op = make_float4(a.x + p.x, a.y + p.y, b.x + q.x, b.y + q.y);
}

// ======================= host =======================
extern "C" void kernel_launch(void* const* d_in, const int* in_sizes, int n_in,
                              void* d_out, int out_size)
{
    const float* x  = (const float*)d_in[0];   // [32,1024,512]
    const float* h0 = (const float*)d_in[1];   // [32,1024]
    const float* W  = (const float*)d_in[2];   // [512,1024]
    const float* R  = (const float*)d_in[3];   // [1024,1024]
    float* out = (float*)d_out;                // [32,1024,1024]

    __nv_bfloat16 *s0h, *s0l, *s1h, *s1l, *xh, *xl, *h0h, *h0l, *wth, *wtl;
    __nv_bfloat16 *ph, *pl, *pth, *ptl, *p32th, *p32tl;
    cudaGetSymbolAddress((void**)&s0h, g_s0h);   cudaGetSymbolAddress((void**)&s0l, g_s0l);
    cudaGetSymbolAddress((void**)&s1h, g_s1h);   cudaGetSymbolAddress((void**)&s1l, g_s1l);
    cudaGetSymbolAddress((void**)&xh,  g_xh);    cudaGetSymbolAddress((void**)&xl,  g_xl);
    cudaGetSymbolAddress((void**)&h0h, g_h0h);   cudaGetSymbolAddress((void**)&h0l, g_h0l);
    cudaGetSymbolAddress((void**)&wth, g_wth);   cudaGetSymbolAddress((void**)&wtl, g_wtl);
    cudaGetSymbolAddress((void**)&ph,  g_ph);    cudaGetSymbolAddress((void**)&pl,  g_pl);
    cudaGetSymbolAddress((void**)&pth, g_pth);   cudaGetSymbolAddress((void**)&ptl, g_ptl);
    cudaGetSymbolAddress((void**)&p32th, g_p32th); cudaGetSymbolAddress((void**)&p32tl, g_p32tl);

    auto P_h  = [&](int i) { return ph  + (size_t)i * 1048576; };
    auto P_l  = [&](int i) { return pl  + (size_t)i * 1048576; };
    auto P_th = [&](int i) { return pth + (size_t)i * 1048576; };
    auto P_tl = [&](int i) { return ptl + (size_t)i * 1048576; };

    // ---- pre-passes: split/transpose operands to bf16 hi/lo ----
    split_x<<<16384, 256>>>(x, xh, xl);
    split_plain<<<32, 256>>>(h0, h0h, h0l);
    split_plain<<<1024, 256>>>(R, P_h(0), P_l(0));
    tsplit<<<dim3(32, 32), dim3(32, 8)>>>(R, P_th(0), P_tl(0), 1024, 1024);
    tsplit<<<dim3(32, 16), dim3(32, 8)>>>(W, wth, wtl, 512, 1024);

    dim3 blk(256);
    dim3 gP(16, 8);      // 1024-row GEMMs, TN=64 -> 128 CTAs
    dim3 gB(8, 256);     // 32768-row GEMMs, TN=128 -> 2048 CTAs

    // ---- R-power chain (row-major and transposed forms) ----
    for (int lv = 1; lv < 5; lv++) {
        tgemm<64, 0><<<gP, blk>>>(P_h(lv-1), P_l(lv-1), P_th(lv-1), P_tl(lv-1),
                                  nullptr, nullptr, P_h(lv), P_l(lv), nullptr,
                                  1024, 1024, 0, 0);
        tgemm<64, 0><<<gP, blk>>>(P_th(lv-1), P_tl(lv-1), P_h(lv-1), P_l(lv-1),
                                  nullptr, nullptr, P_th(lv), P_tl(lv), nullptr,
                                  1024, 1024, 0, 0);
    }
    tgemm<64, 0><<<gP, blk>>>(P_th(4), P_tl(4), P_h(4), P_l(4),
                              nullptr, nullptr, p32th, p32tl, nullptr,
                              1024, 1024, 0, 0);

    // ---- b0 = x @ W (time-major) ----
    tgemm<128, 0><<<gB, blk>>>(xh, xl, wth, wtl, nullptr, nullptr,
                               s0h, s0l, nullptr, BT, 512, 0, 0);

    // ---- fold initial state: rows t=0 += h0 @ R ----
    tgemm<64, 2><<<dim3(16, 1), blk>>>(h0h, h0l, P_th(0), P_tl(0),
                                       s0h, s0l, s0h, s0l, nullptr,
                                       32, 1024, 0, 0);

    // ---- 5 doubling levels, ping-pong s0<->s1 ----
    tgemm<128, 1><<<gB, blk>>>(s0h, s0l, P_th(0), P_tl(0), s0h, s0l, s1h, s1l, nullptr, BT, 1024,  32, 0);
    tgemm<128, 1><<<gB, blk>>>(s1h, s1l, P_th(1), P_tl(1), s1h, s1l, s0h, s0l, nullptr, BT, 1024,  64, 0);
    tgemm<128, 1><<<gB, blk>>>(s0h, s0l, P_th(2), P_tl(2), s0h, s0l, s1h, s1l, nullptr, BT, 1024, 128, 0);
    tgemm<128, 1><<<gB, blk>>>(s1h, s1l, P_th(3), P_tl(3), s1h, s1l, s0h, s0l, nullptr, BT, 1024, 256, 0);
    tgemm<128, 1><<<gB, blk>>>(s0h, s0l, P_th(4), P_tl(4), s0h, s0l, s1h, s1l, nullptr, BT, 1024, 512, 0);

    // ---- sequential scan: 31 chunk-steps with R^32, dual-write to d_out ----
    for (int s = 1; s < 32; s++) {
        size_t po = (size_t)(s - 1) * 1024 * 1024;
        size_t co = (size_t)s * 1024 * 1024;
        tgemm<64, 2><<<gP, blk>>>(s1h + po, s1l + po, p32th, p32tl,
                                  s1h + co, s1l + co, s1h + co, s1l + co, out,
                                  1024, UD, 0, s * 1024);
    }

    // ---- chunk 0 already final: transpose-copy to d_out ----
    copy0<<<1024, 256>>>(s1h, s1l, out);

    (void)in_sizes; (void)n_in; (void)out_size;
}

// round 7
// speedup vs baseline: 4.3234x; 1.3478x over previous
#include <cuda_runtime.h>
#include <cuda_bf16.h>
#include <cstdint>

// Linear RNN h_t = x_t@W + h_{t-1}@R via log-doubling scan, HMMA mma.sync bf16
// hi/lo-split core (3 passes, fp32 accum). R6: BK=64, 3-stage cp.async pipeline
// (1 barrier/segment), XOR-swizzled 128B smem rows, hoisted address math.

#define UD 1024
#define BT 32768

// hi/lo contiguous: lo part lives at a fixed element offset from hi
#define LO_STATE 33554432
#define LO_X     16777216
#define LO_H0    32768
#define LO_P     1048576
#define LO_W     524288

__device__ __nv_bfloat16 g_s0[67108864];     // state ping [hi|lo]
__device__ __nv_bfloat16 g_s1[67108864];     // state pong [hi|lo]
__device__ __nv_bfloat16 g_x [33554432];     // x time-major [hi|lo]
__device__ __nv_bfloat16 g_h0[65536];        // h0 [hi|lo]
__device__ __nv_bfloat16 g_wt[1048576];      // W^T K-major [hi|lo]
__device__ __nv_bfloat16 g_p [5][2097152];   // R^(2^l) row-major [hi|lo]
__device__ __nv_bfloat16 g_pt[5][2097152];   // (R^T)^(2^l) K-major [hi|lo]
__device__ __nv_bfloat16 g_p32t[2097152];    // (R^T)^32 for the scan [hi|lo]

// ---------------- helpers ----------------
__device__ __forceinline__ uint32_t smem_u32(const void* p) {
    uint32_t a;
    asm("{ .reg .u64 t; cvta.to.shared.u64 t, %1; cvt.u32.u64 %0, t; }"
        : "=r"(a) : "l"(p));
    return a;
}
__device__ __forceinline__ void cpa16(uint32_t d, const void* s) {
    asm volatile("cp.async.cg.shared.global [%0], [%1], 16;" :: "r"(d), "l"(s) : "memory");
}
#define CPA_COMMIT() asm volatile("cp.async.commit_group;" ::: "memory")

__device__ __forceinline__ uint32_t pk(__nv_bfloat16 a, __nv_bfloat16 b) {
    return (uint32_t)__bfloat16_as_ushort(a) | ((uint32_t)__bfloat16_as_ushort(b) << 16);
}
__device__ __forceinline__ void split4(float4 v, uint2& h, uint2& l) {
    __nv_bfloat16 h0 = __float2bfloat16(v.x), h1 = __float2bfloat16(v.y);
    __nv_bfloat16 h2 = __float2bfloat16(v.z), h3 = __float2bfloat16(v.w);
    __nv_bfloat16 l0 = __float2bfloat16(v.x - __bfloat162float(h0));
    __nv_bfloat16 l1 = __float2bfloat16(v.y - __bfloat162float(h1));
    __nv_bfloat16 l2 = __float2bfloat16(v.z - __bfloat162float(h2));
    __nv_bfloat16 l3 = __float2bfloat16(v.w - __bfloat162float(h3));
    h.x = pk(h0, h1); h.y = pk(h2, h3);
    l.x = pk(l0, l1); l.y = pk(l2, l3);
}

// ======================= HMMA GEMM =======================
// C[m,n] = sum_k A[m,k]*Bt[n,k]  (Bt K-major [N,K])
// passes: seg phase 0: Ah*Bh, 1: Al*Bh, 2: Ah*Bl (fp32 accum)
// MODE 0: C = A@B
// MODE 1: C[r] = S[r] + (r>=shift ? A[r-shift]@B : 0)
// MODE 2: C[r] = S[r] + A[r]@B ; optional fp32 transposed dual-write to OUT
template<int TN, int MODE>
__global__ void __launch_bounds__(256, 2) tgemm(
    const __nv_bfloat16* __restrict__ A, int loA,
    const __nv_bfloat16* __restrict__ Bm, int loB,
    const __nv_bfloat16* __restrict__ S,
    __nv_bfloat16* __restrict__ C, int loSC,
    float* __restrict__ OUT,
    int M, int Kd, int shift, int rowOff)
{
    constexpr int ABYTES = 128 * 128;          // 128 rows x 64 bf16
    constexpr int BBYTES = TN * 128;
    constexpr int STG    = ABYTES + BBYTES;
    constexpr int NBI    = TN / 32;            // B chunk iterations
    extern __shared__ char smem_[];

    const int tid  = threadIdx.x;
    const int wid  = tid >> 5, lane = tid & 31;
    const int rowTile = blockIdx.y * 128;
    const int colBase = blockIdx.x * TN;
    const int wr = wid >> 1, wc = wid & 1;
    constexpr int WCOL = TN / 2;
    constexpr int NN   = WCOL / 8;
    const int wcBase = wc * WCOL;

    const uint32_t sb = smem_u32(smem_);
    const int nk   = Kd >> 6;
    const int nSeg = 3 * nk;

    // ---- hoisted load addressing (constant across segments) ----
    const __nv_bfloat16* baseA[4];
    uint32_t aoffs[4];
    #pragma unroll
    for (int i = 0; i < 4; i++) {
        int t = tid + i * 256;
        int row = t >> 3, ch = t & 7;
        int r = rowTile + row;
        int ar = (MODE == 1) ? r - shift : r;
        ar = ar < 0 ? 0 : (ar > M - 1 ? M - 1 : ar);
        baseA[i] = A + (size_t)ar * Kd + ch * 8;
        aoffs[i] = row * 128 + ((ch ^ (row & 7)) << 4);
    }
    const __nv_bfloat16* baseB[NBI];
    uint32_t boffs[NBI];
    #pragma unroll
    for (int i = 0; i < NBI; i++) {
        int t = tid + i * 256;
        int row = t >> 3, ch = t & 7;
        baseB[i] = Bm + (size_t)(colBase + row) * Kd + ch * 8;
        boffs[i] = ABYTES + row * 128 + ((ch ^ (row & 7)) << 4);
    }

    auto load_stage = [&](int buf, int seg) {
        int phase = (seg >= nk) + (seg >= 2 * nk);
        int koff  = (seg - phase * nk) * 64;
        int dA = koff + ((phase == 1) ? loA : 0);
        int dB = koff + ((phase == 2) ? loB : 0);
        const uint32_t stb = sb + buf * STG;
        #pragma unroll
        for (int i = 0; i < 4; i++)   cpa16(stb + aoffs[i], baseA[i] + dA);
        #pragma unroll
        for (int i = 0; i < NBI; i++) cpa16(stb + boffs[i], baseB[i] + dB);
    };

    // ---- compute-side smem addressing ----
    const int sw = lane & 7;                      // XOR term for ldmatrix rows
    const uint32_t arow0 = (uint32_t)((wr * 32 + (lane & 15)) * 128);
    const int aunit = (lane >> 4);
    const uint32_t brow0 = (uint32_t)((wcBase + ((lane >> 4) << 3) + (lane & 7)) * 128);
    const int bunit = (lane >> 3) & 1;

    float acc[2][NN][4] = {};

    load_stage(0, 0); CPA_COMMIT();
    load_stage(1, 1); CPA_COMMIT();

    for (int s = 0; s < nSeg; s++) {
        asm volatile("cp.async.wait_group 1;" ::: "memory");
        __syncthreads();
        if (s + 2 < nSeg) load_stage((s + 2) % 3, s + 2);
        CPA_COMMIT();
        const uint32_t abase = sb + (s % 3) * STG;
        #pragma unroll
        for (int k16 = 0; k16 < 4; k16++) {
            uint32_t a[2][4], b[NN][2];
            #pragma unroll
            for (int mi = 0; mi < 2; mi++) {
                uint32_t ad = abase + arow0 + mi * (16 * 128)
                            + (((k16 * 2 + aunit) ^ sw) << 4);
                asm volatile("ldmatrix.sync.aligned.m8n8.x4.shared.b16 {%0,%1,%2,%3}, [%4];"
                    : "=r"(a[mi][0]), "=r"(a[mi][1]), "=r"(a[mi][2]), "=r"(a[mi][3])
                    : "r"(ad));
            }
            #pragma unroll
            for (int bj = 0; bj < NN / 2; bj++) {
                uint32_t bd = abase + ABYTES + brow0 + bj * (16 * 128)
                            + (((k16 * 2 + bunit) ^ sw) << 4);
                asm volatile("ldmatrix.sync.aligned.m8n8.x4.shared.b16 {%0,%1,%2,%3}, [%4];"
                    : "=r"(b[2 * bj][0]), "=r"(b[2 * bj][1]),
                      "=r"(b[2 * bj + 1][0]), "=r"(b[2 * bj + 1][1])
                    : "r"(bd));
            }
            #pragma unroll
            for (int mi = 0; mi < 2; mi++)
                #pragma unroll
                for (int nj = 0; nj < NN; nj++)
                    asm volatile(
                        "mma.sync.aligned.m16n8k16.row.col.f32.bf16.bf16.f32 "
                        "{%0,%1,%2,%3}, {%4,%5,%6,%7}, {%8,%9}, {%0,%1,%2,%3};"
                        : "+f"(acc[mi][nj][0]), "+f"(acc[mi][nj][1]),
                          "+f"(acc[mi][nj][2]), "+f"(acc[mi][nj][3])
                        : "r"(a[mi][0]), "r"(a[mi][1]), "r"(a[mi][2]), "r"(a[mi][3]),
                          "r"(b[nj][0]), "r"(b[nj][1]));
        }
        __syncthreads();
    }

    // ---- epilogue ----
    #pragma unroll
    for (int mi = 0; mi < 2; mi++) {
        #pragma unroll
        for (int half = 0; half < 2; half++) {
            int rr = rowTile + wr * 32 + mi * 16 + half * 8 + (lane >> 2);
            if (rr >= M) continue;
            const bool live = (MODE != 1) || (rr >= shift);
            const size_t rb = (size_t)rr * UD;
            int g = rowOff + rr;
            float* op = (MODE == 2 && OUT != nullptr)
                      ? OUT + (size_t)((g & 31) * 1024 + (g >> 5)) * UD : nullptr;
            #pragma unroll
            for (int nj = 0; nj < NN; nj++) {
                int col = colBase + wcBase + nj * 8 + (lane & 3) * 2;
                float v0 = acc[mi][nj][half * 2];
                float v1 = acc[mi][nj][half * 2 + 1];
                if (MODE >= 1) {
                    __nv_bfloat162 sh2 = *(const __nv_bfloat162*)(S + rb + col);
                    __nv_bfloat162 sl2 = *(const __nv_bfloat162*)(S + loSC + rb + col);
                    float2 fh = __bfloat1622float2(sh2);
                    float2 fl = __bfloat1622float2(sl2);
                    v0 = fh.x + fl.x + (live ? v0 : 0.f);
                    v1 = fh.y + fl.y + (live ? v1 : 0.f);
                }
                __nv_bfloat16 h0_ = __float2bfloat16(v0), h1_ = __float2bfloat16(v1);
                __nv_bfloat16 l0_ = __float2bfloat16(v0 - __bfloat162float(h0_));
                __nv_bfloat16 l1_ = __float2bfloat16(v1 - __bfloat162float(h1_));
                *(uint32_t*)(C + rb + col)        = pk(h0_, h1_);
                *(uint32_t*)(C + loSC + rb + col) = pk(l0_, l1_);
                if (op) { op[col] = v0; op[col + 1] = v1; }
            }
        }
    }
}

// ======================= pre/post kernels =======================
__global__ void split_x(const float* __restrict__ x, __nv_bfloat16* __restrict__ o)
{
    int id = blockIdx.x * 256 + threadIdx.x;
    int r = id >> 7;                                  // time-major row t*32+b
    int c = (id & 127) << 2;
    int b = r & 31, t = r >> 5;
    float4 vv = *(const float4*)(x + (size_t)(b * 1024 + t) * 512 + c);
    uint2 h, l; split4(vv, h, l);
    *(uint2*)(o + (size_t)r * 512 + c) = h;
    *(uint2*)(o + LO_X + (size_t)r * 512 + c) = l;
}

__global__ void split_plain(const float* __restrict__ in,
                            __nv_bfloat16* __restrict__ o, int loOff)
{
    int id = blockIdx.x * 256 + threadIdx.x;
    float4 vv = *(const float4*)(in + (size_t)id * 4);
    uint2 h, l; split4(vv, h, l);
    *(uint2*)(o + (size_t)id * 4) = h;
    *(uint2*)(o + loOff + (size_t)id * 4) = l;
}

__global__ void tsplit(const float* __restrict__ in,
                       __nv_bfloat16* __restrict__ o, int loOff, int K, int N)
{
    __shared__ float tile[32][33];
    int nb = blockIdx.x * 32, kb = blockIdx.y * 32;
    int tx = threadIdx.x, ty = threadIdx.y;
    #pragma unroll
    for (int j = 0; j < 32; j += 8)
        tile[ty + j][tx] = in[(size_t)(kb + ty + j) * N + nb + tx];
    __syncthreads();
    #pragma unroll
    for (int j = 0; j < 32; j += 8) {
        float vv = tile[tx][ty + j];
        size_t off = (size_t)(nb + ty + j) * K + kb + tx;
        __nv_bfloat16 h = __float2bfloat16(vv);
        o[off] = h;
        o[loOff + off] = __float2bfloat16(vv - __bfloat162float(h));
    }
}

__global__ void copy0(const __nv_bfloat16* __restrict__ Sv, float* __restrict__ OUT)
{
    int id = blockIdx.x * 256 + threadIdx.x;
    int g = id >> 8;
    int c = (id & 255) << 2;
    size_t off = (size_t)g * UD + c;
    __nv_bfloat162 h01 = *(const __nv_bfloat162*)(Sv + off);
    __nv_bfloat162 h23 = *(const __nv_bfloat162*)(Sv + off + 2);
    __nv_bfloat162 l01 = *(const __nv_bfloat162*)(Sv + LO_STATE + off);
    __nv_bfloat162 l23 = *(const __nv_bfloat162*)(Sv + LO_STATE + off + 2);
    float2 a = __bfloat1622float2(h01), b = __bfloat1622float2(h23);
    float2 p = __bfloat1622float2(l01), q = __bfloat1622float2(l23);
    float* op = OUT + (size_t)((g & 31) * 1024 + (g >> 5)) * UD + c;
    *(float4*)op = make_float4(a.x + p.x, a.y + p.y, b.x + q.x, b.y + q.y);
}

// ======================= host =======================
extern "C" void kernel_launch(void* const* d_in, const int* in_sizes, int n_in,
                              void* d_out, int out_size)
{
    const float* x  = (const float*)d_in[0];   // [32,1024,512]
    const float* h0 = (const float*)d_in[1];   // [32,1024]
    const float* W  = (const float*)d_in[2];   // [512,1024]
    const float* R  = (const float*)d_in[3];   // [1024,1024]
    float* out = (float*)d_out;                // [32,1024,1024]

    __nv_bfloat16 *s0, *s1, *xs, *h0s, *wt, *p, *pt, *p32t;
    cudaGetSymbolAddress((void**)&s0,  g_s0);
    cudaGetSymbolAddress((void**)&s1,  g_s1);
    cudaGetSymbolAddress((void**)&xs,  g_x);
    cudaGetSymbolAddress((void**)&h0s, g_h0);
    cudaGetSymbolAddress((void**)&wt,  g_wt);
    cudaGetSymbolAddress((void**)&p,   g_p);
    cudaGetSymbolAddress((void**)&pt,  g_pt);
    cudaGetSymbolAddress((void**)&p32t, g_p32t);

    auto P_  = [&](int i) { return p  + (size_t)i * 2097152; };
    auto PT_ = [&](int i) { return pt + (size_t)i * 2097152; };

    constexpr int DS128 = 3 * (128 + 128) * 128;   // 98304
    constexpr int DS64  = 3 * (128 + 64) * 128;    // 73728
    cudaFuncSetAttribute(tgemm<128, 0>, cudaFuncAttributeMaxDynamicSharedMemorySize, DS128);
    cudaFuncSetAttribute(tgemm<128, 1>, cudaFuncAttributeMaxDynamicSharedMemorySize, DS128);
    cudaFuncSetAttribute(tgemm<64, 0>,  cudaFuncAttributeMaxDynamicSharedMemorySize, DS64);
    cudaFuncSetAttribute(tgemm<64, 2>,  cudaFuncAttributeMaxDynamicSharedMemorySize, DS64);

    // ---- pre-passes ----
    split_x<<<16384, 256>>>(x, xs);
    split_plain<<<32, 256>>>(h0, h0s, LO_H0);
    split_plain<<<1024, 256>>>(R, P_(0), LO_P);
    tsplit<<<dim3(32, 32), dim3(32, 8)>>>(R, PT_(0), LO_P, 1024, 1024);
    tsplit<<<dim3(32, 16), dim3(32, 8)>>>(W, wt, LO_W, 512, 1024);

    dim3 blk(256);
    dim3 gP(16, 8);      // 1024-row GEMMs, TN=64
    dim3 gB(8, 256);     // 32768-row GEMMs, TN=128

    // ---- R-power chain (row-major + transposed forms) ----
    for (int lv = 1; lv < 5; lv++) {
        tgemm<64, 0><<<gP, blk, DS64>>>(P_(lv-1), LO_P, PT_(lv-1), LO_P,
                                        nullptr, P_(lv), LO_P, nullptr,
                                        1024, 1024, 0, 0);
        tgemm<64, 0><<<gP, blk, DS64>>>(PT_(lv-1), LO_P, P_(lv-1), LO_P,
                                        nullptr, PT_(lv), LO_P, nullptr,
                                        1024, 1024, 0, 0);
    }
    tgemm<64, 0><<<gP, blk, DS64>>>(PT_(4), LO_P, P_(4), LO_P,
                                    nullptr, p32t, LO_P, nullptr,
                                    1024, 1024, 0, 0);

    // ---- b0 = x @ W (time-major) ----
    tgemm<128, 0><<<gB, blk, DS128>>>(xs, LO_X, wt, LO_W, nullptr,
                                      s0, LO_STATE, nullptr, BT, 512, 0, 0);

    // ---- fold initial state: rows t=0 += h0 @ R ----
    tgemm<64, 2><<<dim3(16, 1), blk, DS64>>>(h0s, LO_H0, PT_(0), LO_P,
                                             s0, s0, LO_STATE, nullptr,
                                             32, 1024, 0, 0);

    // ---- 5 doubling levels, ping-pong s0<->s1 ----
    tgemm<128, 1><<<gB, blk, DS128>>>(s0, LO_STATE, PT_(0), LO_P, s0, s1, LO_STATE, nullptr, BT, 1024,  32, 0);
    tgemm<128, 1><<<gB, blk, DS128>>>(s1, LO_STATE, PT_(1), LO_P, s1, s0, LO_STATE, nullptr, BT, 1024,  64, 0);
    tgemm<128, 1><<<gB, blk, DS128>>>(s0, LO_STATE, PT_(2), LO_P, s0, s1, LO_STATE, nullptr, BT, 1024, 128, 0);
    tgemm<128, 1><<<gB, blk, DS128>>>(s1, LO_STATE, PT_(3), LO_P, s1, s0, LO_STATE, nullptr, BT, 1024, 256, 0);
    tgemm<128, 1><<<gB, blk, DS128>>>(s0, LO_STATE, PT_(4), LO_P, s0, s1, LO_STATE, nullptr, BT, 1024, 512, 0);

    // ---- sequential scan: 31 chunk-steps with R^32, dual-write to d_out ----
    for (int s = 1; s < 32; s++) {
        size_t po = (size_t)(s - 1) * 1024 * 1024;
        size_t co = (size_t)s * 1024 * 1024;
        tgemm<64, 2><<<gP, blk, DS64>>>(s1 + po, LO_STATE, p32t, LO_P,
                                        s1 + co, s1 + co, LO_STATE, out,
                                        1024, 1024, 0, s * 1024);
    }

    // ---- chunk 0 already final: transpose-copy to d_out ----
    copy0<<<1024, 256>>>(s1, out);

    (void)in_sizes; (void)n_in; (void)out_size;
}